// round 1
// baseline (speedup 1.0000x reference)
#include <cuda_runtime.h>
#include <math.h>

#define HH 512
#define WW 512
#define CC 3
#define NN 32
#define HW (HH*WW)
#define HWC (HH*WW*CC)
#define NPIX (NN*HH*WW)

// Scratch: masked_inter buffer (3 MB, L2-resident) + reduction accumulator.
__device__ float g_mi[HWC];
__device__ double g_acc;

__global__ void __launch_bounds__(256) prep_kernel(const float* __restrict__ mask,
                                                   const float* __restrict__ inter) {
    int i = blockIdx.x * blockDim.x + threadIdx.x;
    if (i == 0) g_acc = 0.0;
    const int n4 = HWC / 4;
    if (i < n4) {
        float4 m = ((const float4*)mask)[i];
        float4 t = ((const float4*)inter)[i];
        float4 r;
        r.x = m.x * t.x; r.y = m.y * t.y; r.z = m.z * t.z; r.w = m.w * t.w;
        ((float4*)g_mi)[i] = r;
    }
}

__global__ void __launch_bounds__(256) main_kernel(const float* __restrict__ image,
                                                   const float* __restrict__ transforms,
                                                   float* __restrict__ out) {
    int p = blockIdx.x * 256 + threadIdx.x;      // pixel id in [0, N*H*W)
    int n   = p >> 18;                           // / (512*512)
    int rem = p & (HW - 1);
    int h   = rem >> 9;
    int w   = rem & (WW - 1);

    const float* t = transforms + n * 8;
    float a0 = __ldg(t + 0), a1 = __ldg(t + 1), a2 = __ldg(t + 2);
    float b0 = __ldg(t + 3), b1 = __ldg(t + 4), b2 = __ldg(t + 5);
    float c0 = __ldg(t + 6), c1 = __ldg(t + 7);

    float fx = (float)w, fy = (float)h;
    float inv = 1.0f / (c0 * fx + c1 * fy + 1.0f);
    float sx = (a0 * fx + a1 * fy + a2) * inv;
    float sy = (b0 * fx + b1 * fy + b2) * inv;

    float x0 = floorf(sx), y0 = floorf(sy);
    float wx = sx - x0, wy = sy - y0;

    float v[4][3];
    #pragma unroll
    for (int dy = 0; dy < 2; dy++) {
        #pragma unroll
        for (int dx = 0; dx < 2; dx++) {
            float xc = x0 + (float)dx;
            float yc = y0 + (float)dy;
            float* vv = v[dy * 2 + dx];
            bool valid = (xc >= 0.0f) & (xc <= (float)(WW - 1)) &
                         (yc >= 0.0f) & (yc <= (float)(HH - 1));
            if (valid) {
                // inside bounds: clip is identity; coords are exact integers
                int base = (((int)yc) * WW + ((int)xc)) * CC;
                vv[0] = g_mi[base + 0];
                vv[1] = g_mi[base + 1];
                vv[2] = g_mi[base + 2];
            } else {
                vv[0] = 0.0f; vv[1] = 0.0f; vv[2] = 0.0f;
            }
        }
    }

    float omwx = 1.0f - wx, omwy = 1.0f - wy;
    int ib = rem * CC;           // image index for (h,w)
    long long ob = (long long)p * CC;

    float s = 0.0f;
    #pragma unroll
    for (int c = 0; c < 3; c++) {
        float img   = __ldg(image + ib + c);
        float wimg  = atanhf(img);
        float top   = v[0][c] * omwx + v[1][c] * wx;
        float bot   = v[2][c] * omwx + v[3][c] * wx;
        float warp  = top * omwy + bot * wy;
        float con   = tanhf(wimg + warp);
        out[ob + c] = con;
        float d = img - con;
        s += d * d;
    }

    // Block reduction of squared perturbation
    #pragma unroll
    for (int o = 16; o > 0; o >>= 1)
        s += __shfl_down_sync(0xffffffffu, s, o);
    __shared__ float ws[8];
    int lane = threadIdx.x & 31;
    int wid  = threadIdx.x >> 5;
    if (lane == 0) ws[wid] = s;
    __syncthreads();
    if (wid == 0) {
        s = (lane < 8) ? ws[lane] : 0.0f;
        #pragma unroll
        for (int o = 4; o > 0; o >>= 1)
            s += __shfl_down_sync(0xffffffffu, s, o);
        if (lane == 0) atomicAdd(&g_acc, (double)s);
    }
}

__global__ void fin_kernel(float* __restrict__ out, int out_size) {
    // non_smoothness is exactly 0 (empty slice on size-1 batch axis)
    out[out_size - 1] = 0.01f * sqrtf((float)g_acc);
}

extern "C" void kernel_launch(void* const* d_in, const int* in_sizes, int n_in,
                              void* d_out, int out_size) {
    const float* image      = (const float*)d_in[0];
    const float* mask       = (const float*)d_in[1];
    const float* inter      = (const float*)d_in[2];
    const float* transforms = (const float*)d_in[3];
    float* out = (float*)d_out;

    prep_kernel<<<(HWC / 4 + 255) / 256, 256>>>(mask, inter);
    main_kernel<<<NPIX / 256, 256>>>(image, transforms, out);
    fin_kernel<<<1, 1>>>(out, out_size);
}

// round 14
// speedup vs baseline: 1.9388x; 1.9388x over previous
#include <cuda_runtime.h>
#include <math.h>

#define HH 512
#define WW 512
#define CC 3
#define NN 32
#define HW (HH*WW)
#define HWC (HH*WW*CC)
#define NPIX (NN*HH*WW)

// float4-padded masked_inter (RGBA, pad=0) for single-LDG.128 bilinear taps.
__device__ float4 g_mi4[HW];
__device__ double g_acc;

// tanh via MUFU ex2 path: rel err ~1e-7, exact saturation at +/-1.
__device__ __forceinline__ float fast_tanh(float x) {
    float e = __expf(2.0f * x);
    return 1.0f - __fdividef(2.0f, e + 1.0f);
}

__global__ void __launch_bounds__(256) prep_kernel(const float* __restrict__ mask,
                                                   const float* __restrict__ inter) {
    int i = blockIdx.x * blockDim.x + threadIdx.x;   // one thread = 4 pixels
    if (i == 0) g_acc = 0.0;
    if (i >= HW / 4) return;
    const float4* m4 = (const float4*)mask;
    const float4* t4 = (const float4*)inter;
    float m[12], t[12];
    #pragma unroll
    for (int k = 0; k < 3; k++) {
        float4 mm = m4[i * 3 + k];
        float4 tt = t4[i * 3 + k];
        m[k*4+0]=mm.x; m[k*4+1]=mm.y; m[k*4+2]=mm.z; m[k*4+3]=mm.w;
        t[k*4+0]=tt.x; t[k*4+1]=tt.y; t[k*4+2]=tt.z; t[k*4+3]=tt.w;
    }
    #pragma unroll
    for (int p = 0; p < 4; p++) {
        float4 r;
        r.x = m[p*3+0] * t[p*3+0];
        r.y = m[p*3+1] * t[p*3+1];
        r.z = m[p*3+2] * t[p*3+2];
        r.w = 0.0f;
        g_mi4[i * 4 + p] = r;
    }
}

__global__ void __launch_bounds__(256) main_kernel(const float* __restrict__ image,
                                                   const float* __restrict__ transforms,
                                                   float* __restrict__ out) {
    __shared__ float s_t[NN * 8];
    int tid = threadIdx.x;
    s_t[tid] = __ldg(transforms + tid);   // 32*8 == 256 == blockDim
    int rem = blockIdx.x * 256 + tid;     // spatial pixel id
    int h = rem >> 9;
    int w = rem & (WW - 1);
    float fx = (float)w, fy = (float)h;

    // per-pixel loads + atanh, done ONCE for all 32 transforms
    float img0 = __ldg(image + rem * 3 + 0);
    float img1 = __ldg(image + rem * 3 + 1);
    float img2 = __ldg(image + rem * 3 + 2);
    float wi0 = atanhf(img0);
    float wi1 = atanhf(img1);
    float wi2 = atanhf(img2);
    __syncthreads();

    float s = 0.0f;
    #pragma unroll 1
    for (int n = 0; n < NN; n++) {
        const float* t = s_t + n * 8;
        float a0 = t[0], a1 = t[1], a2 = t[2];
        float b0 = t[3], b1 = t[4], b2 = t[5];
        float c0 = t[6], c1 = t[7];

        float inv = 1.0f / (c0 * fx + c1 * fy + 1.0f);
        float sx = (a0 * fx + a1 * fy + a2) * inv;
        float sy = (b0 * fx + b1 * fy + b2) * inv;

        float x0f = floorf(sx), y0f = floorf(sy);
        float wx = sx - x0f, wy = sy - y0f;
        int xi = (int)x0f, yi = (int)y0f;

        bool vx0 = (x0f >= 0.0f)  & (x0f <= (float)(WW - 1));
        bool vx1 = (x0f >= -1.0f) & (x0f <= (float)(WW - 2));
        bool vy0 = (y0f >= 0.0f)  & (y0f <= (float)(HH - 1));
        bool vy1 = (y0f >= -1.0f) & (y0f <= (float)(HH - 2));

        float4 z = make_float4(0.f, 0.f, 0.f, 0.f);
        float4 v00 = z, v01 = z, v10 = z, v11 = z;
        int base = yi * WW + xi;
        if (vx0 & vy0) v00 = g_mi4[base];
        if (vx1 & vy0) v01 = g_mi4[base + 1];
        if (vx0 & vy1) v10 = g_mi4[base + WW];
        if (vx1 & vy1) v11 = g_mi4[base + WW + 1];

        float omwx = 1.0f - wx, omwy = 1.0f - wy;
        float w00 = omwx * omwy, w01 = wx * omwy;
        float w10 = omwx * wy,   w11 = wx * wy;

        float warp0 = v00.x * w00 + v01.x * w01 + v10.x * w10 + v11.x * w11;
        float warp1 = v00.y * w00 + v01.y * w01 + v10.y * w10 + v11.y * w11;
        float warp2 = v00.z * w00 + v01.z * w01 + v10.z * w10 + v11.z * w11;

        float c0o = fast_tanh(wi0 + warp0);
        float c1o = fast_tanh(wi1 + warp1);
        float c2o = fast_tanh(wi2 + warp2);

        int ob = (n << 18) * 3 + rem * 3;   // n*HWC + rem*3  (fits in int)
        out[ob + 0] = c0o;
        out[ob + 1] = c1o;
        out[ob + 2] = c2o;

        float d0 = img0 - c0o, d1 = img1 - c1o, d2 = img2 - c2o;
        s += d0 * d0 + d1 * d1 + d2 * d2;
    }

    // block reduction (once per thread for all 32 n)
    #pragma unroll
    for (int o = 16; o > 0; o >>= 1)
        s += __shfl_down_sync(0xffffffffu, s, o);
    __shared__ float ws[8];
    int lane = tid & 31, wid = tid >> 5;
    if (lane == 0) ws[wid] = s;
    __syncthreads();
    if (wid == 0) {
        s = (lane < 8) ? ws[lane] : 0.0f;
        #pragma unroll
        for (int o = 4; o > 0; o >>= 1)
            s += __shfl_down_sync(0xffffffffu, s, o);
        if (lane == 0) atomicAdd(&g_acc, (double)s);
    }
}

__global__ void fin_kernel(float* __restrict__ out, int out_size) {
    // non_smoothness is exactly 0 (empty slice on size-1 batch axis)
    out[out_size - 1] = 0.01f * sqrtf((float)g_acc);
}

extern "C" void kernel_launch(void* const* d_in, const int* in_sizes, int n_in,
                              void* d_out, int out_size) {
    const float* image      = (const float*)d_in[0];
    const float* mask       = (const float*)d_in[1];
    const float* inter      = (const float*)d_in[2];
    const float* transforms = (const float*)d_in[3];
    float* out = (float*)d_out;

    prep_kernel<<<(HW / 4 + 255) / 256, 256>>>(mask, inter);
    main_kernel<<<HW / 256, 256>>>(image, transforms, out);
    fin_kernel<<<1, 1>>>(out, out_size);
}